// round 14
// baseline (speedup 1.0000x reference)
#include <cuda_runtime.h>
#include <cuda_fp16.h>

#define Bsz   4
#define Nn    20000
#define Ee    320000
#define CINc  32
#define COUTc 32
#define Kk    16
#define Mm    2
#define BN    (Bsz * Nn)
#define NTm   40000      // tiles per measure = Bsz * Ee / 32

// Scratch. Channel-permuted layout: slot pi(r) = 4*(r&7) + (r>>3)
__device__ float   g_fout[BN * CINc];         // fp32 accumulator, permuted channels
__device__ __half  g_fTh[BN * CINc];          // fp16 fT, permuted channels, 64B/row
__device__ __half2 g_combh[Mm * BN * Kk];     // (bc,bs) per k: 64B per (m,node)
__device__ float4  g_geo[BN];                 // {x, y, nvx, nvy}
__device__ unsigned g_ctr[2];                 // dynamic tile queues (per measure)

__device__ __forceinline__ unsigned packh2(float lo, float hi) {
    __half2 h = __floats2half2_rn(lo, hi);
    return *reinterpret_cast<unsigned*>(&h);
}

__device__ __forceinline__ unsigned h2u(__half2 h) {
    return *reinterpret_cast<unsigned*>(&h);
}

__device__ __forceinline__ void mma_f16(float c[4], const unsigned a[4],
                                        unsigned b0, unsigned b1) {
    asm volatile(
        "mma.sync.aligned.m16n8k16.row.col.f32.f16.f16.f32 "
        "{%0,%1,%2,%3}, {%4,%5,%6,%7}, {%8,%9}, {%0,%1,%2,%3};"
        : "+f"(c[0]), "+f"(c[1]), "+f"(c[2]), "+f"(c[3])
        : "r"(a[0]), "r"(a[1]), "r"(a[2]), "r"(a[3]), "r"(b0), "r"(b1));
}

// ---------------------------------------------------------------------------
// Kernel 1: fT (fp16, permuted) + zero fout + pack comb (half2) + geo + ctr
// ---------------------------------------------------------------------------
__global__ void prep_kernel(const float* __restrict__ f,
                            const float* __restrict__ bc,
                            const float* __restrict__ bs,
                            const float* __restrict__ nodes,
                            const float* __restrict__ nvec)
{
    __shared__ float tile[32][33];
    const int b   = blockIdx.y;
    const int n0  = blockIdx.x * 32;
    const int tx  = threadIdx.x;
    const int ty  = threadIdx.y;
    const int tid = ty * 32 + tx;

    if (blockIdx.x == 0 && blockIdx.y == 0 && tid < 2) g_ctr[tid] = 0u;

#pragma unroll
    for (int r = 0; r < 4; r++) {
        int ci = ty + 8 * r;
        tile[ci][tx] = f[((long)b * CINc + ci) * Nn + n0 + tx];
    }

    if (tid < 32) {
        const long node = (long)b * Nn + n0 + tid;
        const float2 p  = reinterpret_cast<const float2*>(nodes)[node];
        const float2 nv = reinterpret_cast<const float2*>(nvec)[node];
        g_geo[node] = make_float4(p.x, p.y, nv.x, nv.y);
    }

    {
        const int nl = tid >> 3;
        const int pj = tid & 7;
        const long node = (long)b * Nn + n0 + nl;
        const float4 A = *reinterpret_cast<const float4*>(&bc[node * 32 + pj * 4]);
        const float4 B = *reinterpret_cast<const float4*>(&bs[node * 32 + pj * 4]);
        __half2* c0 = &g_combh[(0L * BN + node) * Kk + 2 * pj];
        __half2* c1 = &g_combh[(1L * BN + node) * Kk + 2 * pj];
        c0[0] = __floats2half2_rn(A.x, B.x);
        c0[1] = __floats2half2_rn(A.z, B.z);
        c1[0] = __floats2half2_rn(A.y, B.y);
        c1[1] = __floats2half2_rn(A.w, B.w);
    }

    __syncthreads();
    const int pix = 4 * (tx & 7) + (tx >> 3);
#pragma unroll
    for (int r = 0; r < 4; r++) {
        int nl = ty + 8 * r;
        long base = ((long)b * Nn + n0 + nl) * CINc;
        g_fTh[base + pix] = __float2half(tile[tx][nl]);
        g_fout[base + tx] = 0.0f;
    }
}

// ---------------------------------------------------------------------------
__device__ __forceinline__ float loadW(const float* __restrict__ wc,
                                       const float* __restrict__ ws,
                                       int r, int c, int m)
{
    return (c < 16) ? 2.0f * __ldg(&wc[r * 32 + c * 2 + m])
                    : 2.0f * __ldg(&ws[r * 32 + (c - 16) * 2 + m]);
}

// ---------------------------------------------------------------------------
// Kernel 2: edge scatter, fp16 mma, pipelined, dynamic queue, ping-pong smem.
// ---------------------------------------------------------------------------
__global__ void __launch_bounds__(128) edge_kernel(
    const int*   __restrict__ de,
    const float* __restrict__ nodew,
    const float* __restrict__ wc,
    const float* __restrict__ ws,
    const float* __restrict__ w0)
{
    __shared__ __align__(16) __half pqin[2][4][32][40];  // [buf][warp][edge][P|Q]
    __shared__ __align__(16) int2   nsb[2][4][32];       // {tn, sn}
    __shared__ float sgb[2][4][32];

    const int lane = threadIdx.x & 31;
    const int wid  = threadIdx.x >> 5;

    const int gw = blockIdx.x * 4 + wid;
    const int m  = (gw >= 5000) ? 1 : 0;

    const int gid = lane >> 2;
    const int tq  = lane & 3;

    // A fragments (half): [mt][chunk c][4]
    unsigned afr[2][2][4];
#pragma unroll
    for (int mt = 0; mt < 2; mt++)
#pragma unroll
        for (int c = 0; c < 2; c++) {
            const int r0 = mt * 16 + gid, r1 = r0 + 8;
            const int k0 = c * 16 + 2 * tq;
            const int k1 = k0 + 8;
            afr[mt][c][0] = packh2(loadW(wc, ws, r0, k0, m), loadW(wc, ws, r0, k0 + 1, m));
            afr[mt][c][1] = packh2(loadW(wc, ws, r1, k0, m), loadW(wc, ws, r1, k0 + 1, m));
            afr[mt][c][2] = packh2(loadW(wc, ws, r0, k1, m), loadW(wc, ws, r0, k1 + 1, m));
            afr[mt][c][3] = packh2(loadW(wc, ws, r1, k1, m), loadW(wc, ws, r1, k1 + 1, m));
        }

    const float w00 = __ldg(&w0[(gid +  0) * 2 + m]) + 1.0f;
    const float w01 = __ldg(&w0[(gid +  8) * 2 + m]) + 1.0f;
    const float w02 = __ldg(&w0[(gid + 16) * 2 + m]) + 1.0f;
    const float w03 = __ldg(&w0[(gid + 24) * 2 + m]) + 1.0f;

    const __half2* comb = g_combh + (long)m * BN * Kk;
    const int4*    de4  = reinterpret_cast<const int4*>(de);

    const int eo = lane >> 2;     // PQ: edge-of-8
    const int pj = lane & 3;      // PQ: 16B quad

    // ---- prologue: claim first tile + preload its edge record ----
    unsigned t = 0;
    if (lane == 0) t = atomicAdd(&g_ctr[m], 1u);
    t = __shfl_sync(0xffffffffu, t, 0);
    int4 dv = make_int4(0, 0, 0, 0);
    float nwv = 0.0f;
    if (t < NTm) {
        dv  = __ldg(&de4[(long)t * 32 + lane]);
        nwv = __ldg(&nodew[((long)t * 32 + lane) * 2 + m]);
    }

    int pb = 0;   // ping-pong buffer index
    while (t < NTm) {
        __half (*pin)[40] = pqin[pb][wid];
        int2*  nsw = nsb[pb][wid];
        float* sgw = sgb[pb][wid];

        // claim next tile + prefetch its record (hidden behind PQ + MMA)
        unsigned t1 = 0;
        if (lane == 0) t1 = atomicAdd(&g_ctr[m], 1u);
        t1 = __shfl_sync(0xffffffffu, t1, 0);

        const int b  = (int)(t / 10000u);
        const int tn = b * Nn + (m ? dv.y : dv.x);
        const int sn = b * Nn + (m ? dv.w : dv.z);
        nsw[lane] = make_int2(tn, sn);

        // geo gathers: issued now, consumed after PQ
        const float4 gt = g_geo[tn];
        const float4 gs = g_geo[sn];

        int4 dvn = dv; float nwn = nwv;
        if (t1 < NTm) {
            dvn = __ldg(&de4[(long)t1 * 32 + lane]);
            nwn = __ldg(&nodew[((long)t1 * 32 + lane) * 2 + m]);
        }
        __syncwarp();   // nsw visible

        // ---- PQ phase: 4 iterations x 8 edges; lane = (eo, pj) ----
#pragma unroll
        for (int pr = 0; pr < 4; pr++) {
            const int e   = pr * 8 + eo;
            const int2 ns = nsw[e];
            const uint2 Tu0 = *reinterpret_cast<const uint2*>(&comb[(long)ns.x * Kk + 4 * pj]);
            const uint2 Tu1 = *reinterpret_cast<const uint2*>(&comb[(long)ns.x * Kk + 4 * pj + 2]);
            const uint2 Su0 = *reinterpret_cast<const uint2*>(&comb[(long)ns.y * Kk + 4 * pj]);
            const uint2 Su1 = *reinterpret_cast<const uint2*>(&comb[(long)ns.y * Kk + 4 * pj + 2]);
            const __half2 T[4] = {*(__half2*)&Tu0.x, *(__half2*)&Tu0.y,
                                  *(__half2*)&Tu1.x, *(__half2*)&Tu1.y};
            const __half2 S[4] = {*(__half2*)&Su0.x, *(__half2*)&Su0.y,
                                  *(__half2*)&Su1.x, *(__half2*)&Su1.y};
            __half P[4], Q[4];
#pragma unroll
            for (int k = 0; k < 4; k++) {
                const __half2 pp = __hmul2(T[k], S[k]);                    // (bct*bcs, bst*bss)
                const __half2 qq = __hmul2(T[k], __lowhigh2highlow(S[k])); // (bct*bss, bst*bcs)
                P[k] = __hadd(__low2half(pp), __high2half(pp));
                Q[k] = __hsub(__low2half(qq), __high2half(qq));
            }
            *reinterpret_cast<uint2*>(&pin[e][4 * pj]) =
                make_uint2(h2u(__halves2half2(P[0], P[1])), h2u(__halves2half2(P[2], P[3])));
            *reinterpret_cast<uint2*>(&pin[e][16 + 4 * pj]) =
                make_uint2(h2u(__halves2half2(Q[0], Q[1])), h2u(__halves2half2(Q[2], Q[3])));
        }

        // ---- geometry math (geo arrived during PQ) ----
        {
            const float dx = gt.x - gs.x, dy = gt.y - gs.y;
            const float r2 = fmaf(dx, dx, fmaf(dy, dy, 1e-6f));
            const float gr = fmaf(dx, gs.z, dy * gs.w) / r2;
            sgw[lane] = gr * nwv;
        }
        __syncwarp();   // pin + sgw visible

        // ---- MMA (m16n8k16) + fused epilogue per nt ----
#pragma unroll
        for (int nt = 0; nt < 4; nt++) {
            const __half* prow = pin[nt * 8 + gid];
            float acc0[4] = {0.f, 0.f, 0.f, 0.f};   // rows gid, gid+8
            float acc1[4] = {0.f, 0.f, 0.f, 0.f};   // rows gid+16, gid+24
#pragma unroll
            for (int c = 0; c < 2; c++) {
                const unsigned b0 = *reinterpret_cast<const unsigned*>(&prow[16 * c + 2 * tq]);
                const unsigned b1 = *reinterpret_cast<const unsigned*>(&prow[16 * c + 2 * tq + 8]);
                mma_f16(acc0, afr[0][c], b0, b1);
                mma_f16(acc1, afr[1][c], b0, b1);
            }
            const int ed = nt * 8 + 2 * tq;
#pragma unroll
            for (int h = 0; h < 2; h++) {
                const int2 ns  = nsw[ed + h];
                const float sg = sgw[ed + h];
                const uint2 fu = *reinterpret_cast<const uint2*>(&g_fTh[(long)ns.y * 32 + 4 * gid]);
                const float2 f01 = __half22float2(*(const __half2*)&fu.x);
                const float2 f23 = __half22float2(*(const __half2*)&fu.y);
                const float v0 = (w00 + acc0[h])     * f01.x * sg;
                const float v1 = (w01 + acc0[2 + h]) * f01.y * sg;
                const float v2 = (w02 + acc1[h])     * f23.x * sg;
                const float v3 = (w03 + acc1[2 + h]) * f23.y * sg;
                float* dst = &g_fout[(long)ns.x * 32 + 4 * gid];
                asm volatile(
                    "red.global.add.v4.f32 [%0], {%1, %2, %3, %4};"
                    :: "l"(dst), "f"(v0), "f"(v1), "f"(v2), "f"(v3)
                    : "memory");
            }
        }
        // no trailing syncwarp: next tile writes the other buffer

        t = t1; dv = dvn; nwv = nwn; pb ^= 1;
    }
}

// ---------------------------------------------------------------------------
// Kernel 3: out[b,o,n] = sum_i w[o,i] * f_out_permuted[b,n,pi(i)] + bias[o]
// 64-node tiles, float4 fill. grid (Nn/64+1, B) handles N=20000 (312.5 tiles).
// ---------------------------------------------------------------------------
__global__ void __launch_bounds__(256) out_kernel(
    const float* __restrict__ wk,
    const float* __restrict__ bias,
    float* __restrict__ out)
{
    __shared__ float fsm[64][33];
    __shared__ float wsm[COUTc][CINc];

    const int b   = blockIdx.y;
    const int n0  = blockIdx.x * 64;
    const int tid = threadIdx.x;
    const int nn  = min(64, Nn - n0);   // tail tile: Nn % 64 = 32

    for (int j = tid; j < COUTc * CINc; j += 256) {
        const int o = j / CINc, i = j % CINc;
        wsm[o][4 * (i & 7) + (i >> 3)] = wk[j];
    }

    // fill: 64 nodes x 8 float4 = 512 float4 loads, 2 per thread
#pragma unroll
    for (int j = 0; j < 2; j++) {
        const int idx = j * 256 + tid;       // 0..511
        const int nl = idx >> 3, q = idx & 7;
        if (nl < nn) {
            const float4 v = *reinterpret_cast<const float4*>(
                &g_fout[((long)b * Nn + n0 + nl) * CINc + q * 4]);
            fsm[nl][q * 4 + 0] = v.x;
            fsm[nl][q * 4 + 1] = v.y;
            fsm[nl][q * 4 + 2] = v.z;
            fsm[nl][q * 4 + 3] = v.w;
        }
    }
    __syncthreads();

    // compute: 64 nodes x 32 outputs = 2048 elems, 8 per thread
    // warp w handles o = w*4 .. w*4+3? Keep o uniform per warp: idx>>6 = o-pair
#pragma unroll
    for (int j = 0; j < 8; j++) {
        const int idx = j * 256 + tid;       // 0..2047
        const int o = idx >> 6, nl = idx & 63;   // o uniform within warp half
        if (nl < nn) {
            float acc = bias[o];
#pragma unroll
            for (int i = 0; i < CINc; i++)
                acc = fmaf(wsm[o][i], fsm[nl][i], acc);
            out[((long)b * COUTc + o) * Nn + n0 + nl] = acc;
        }
    }
}

// ---------------------------------------------------------------------------
extern "C" void kernel_launch(void* const* d_in, const int* in_sizes, int n_in,
                              void* d_out, int out_size)
{
    const float* f    = (const float*)d_in[0];
    const float* bc   = (const float*)d_in[1];
    const float* bs   = (const float*)d_in[2];
    const float* nodes= (const float*)d_in[4];
    const float* nvec = (const float*)d_in[5];
    const int*   de   = (const int*)  d_in[6];
    const float* nw   = (const float*)d_in[7];
    const float* wc   = (const float*)d_in[8];
    const float* ws   = (const float*)d_in[9];
    const float* w0   = (const float*)d_in[10];
    const float* wk   = (const float*)d_in[11];
    const float* wb   = (const float*)d_in[12];
    float* out = (float*)d_out;

    prep_kernel<<<dim3(Nn / 32, Bsz), dim3(32, 8)>>>(f, bc, bs, nodes, nvec);
    edge_kernel<<<2500, 128>>>(de, nw, wc, ws, w0);
    out_kernel<<<dim3((Nn + 63) / 64, Bsz), 256>>>(wk, wb, out);
}

// round 15
// speedup vs baseline: 1.0129x; 1.0129x over previous
#include <cuda_runtime.h>
#include <cuda_fp16.h>

#define Bsz   4
#define Nn    20000
#define Ee    320000
#define CINc  32
#define COUTc 32
#define Kk    16
#define Mm    2
#define BN    (Bsz * Nn)
#define NTm   40000      // tiles per measure = Bsz * Ee / 32

// Scratch. Channel-permuted layout: slot pi(r) = 4*(r&7) + (r>>3)
__device__ float   g_fout[BN * CINc];         // fp32 accumulator, permuted channels
__device__ __half  g_fTh[BN * CINc];          // fp16 fT, permuted channels, 64B/row
__device__ __half2 g_combh[Mm * BN * Kk];     // (bc,bs) per k: 64B per (m,node)
__device__ float4  g_geo[BN];                 // {x, y, nvx, nvy}
__device__ unsigned g_ctr[2];                 // dynamic tile queues (per measure)

__device__ __forceinline__ unsigned packh2(float lo, float hi) {
    __half2 h = __floats2half2_rn(lo, hi);
    return *reinterpret_cast<unsigned*>(&h);
}

__device__ __forceinline__ unsigned h2u(__half2 h) {
    return *reinterpret_cast<unsigned*>(&h);
}

__device__ __forceinline__ void mma_f16(float c[4], const unsigned a[4],
                                        unsigned b0, unsigned b1) {
    asm volatile(
        "mma.sync.aligned.m16n8k16.row.col.f32.f16.f16.f32 "
        "{%0,%1,%2,%3}, {%4,%5,%6,%7}, {%8,%9}, {%0,%1,%2,%3};"
        : "+f"(c[0]), "+f"(c[1]), "+f"(c[2]), "+f"(c[3])
        : "r"(a[0]), "r"(a[1]), "r"(a[2]), "r"(a[3]), "r"(b0), "r"(b1));
}

// ---------------------------------------------------------------------------
// Kernel 1: fT (fp16, permuted) + zero fout + pack comb (half2) + geo + ctr
// ---------------------------------------------------------------------------
__global__ void prep_kernel(const float* __restrict__ f,
                            const float* __restrict__ bc,
                            const float* __restrict__ bs,
                            const float* __restrict__ nodes,
                            const float* __restrict__ nvec)
{
    __shared__ float tile[32][33];
    const int b   = blockIdx.y;
    const int n0  = blockIdx.x * 32;
    const int tx  = threadIdx.x;
    const int ty  = threadIdx.y;
    const int tid = ty * 32 + tx;

    if (blockIdx.x == 0 && blockIdx.y == 0 && tid < 2) g_ctr[tid] = 0u;

#pragma unroll
    for (int r = 0; r < 4; r++) {
        int ci = ty + 8 * r;
        tile[ci][tx] = f[((long)b * CINc + ci) * Nn + n0 + tx];
    }

    if (tid < 32) {
        const long node = (long)b * Nn + n0 + tid;
        const float2 p  = reinterpret_cast<const float2*>(nodes)[node];
        const float2 nv = reinterpret_cast<const float2*>(nvec)[node];
        g_geo[node] = make_float4(p.x, p.y, nv.x, nv.y);
    }

    {
        const int nl = tid >> 3;
        const int pj = tid & 7;
        const long node = (long)b * Nn + n0 + nl;
        const float4 A = *reinterpret_cast<const float4*>(&bc[node * 32 + pj * 4]);
        const float4 B = *reinterpret_cast<const float4*>(&bs[node * 32 + pj * 4]);
        __half2* c0 = &g_combh[(0L * BN + node) * Kk + 2 * pj];
        __half2* c1 = &g_combh[(1L * BN + node) * Kk + 2 * pj];
        c0[0] = __floats2half2_rn(A.x, B.x);
        c0[1] = __floats2half2_rn(A.z, B.z);
        c1[0] = __floats2half2_rn(A.y, B.y);
        c1[1] = __floats2half2_rn(A.w, B.w);
    }

    __syncthreads();
    const int pix = 4 * (tx & 7) + (tx >> 3);
#pragma unroll
    for (int r = 0; r < 4; r++) {
        int nl = ty + 8 * r;
        long base = ((long)b * Nn + n0 + nl) * CINc;
        g_fTh[base + pix] = __float2half(tile[tx][nl]);
        g_fout[base + tx] = 0.0f;
    }
}

// ---------------------------------------------------------------------------
__device__ __forceinline__ float loadW(const float* __restrict__ wc,
                                       const float* __restrict__ ws,
                                       int r, int c, int m)
{
    return (c < 16) ? 2.0f * __ldg(&wc[r * 32 + c * 2 + m])
                    : 2.0f * __ldg(&ws[r * 32 + (c - 16) * 2 + m]);
}

// ---------------------------------------------------------------------------
// Kernel 2: edge scatter, fp16 mma, pipelined, dynamic tile queue. (R13 form)
// ---------------------------------------------------------------------------
__global__ void __launch_bounds__(128) edge_kernel(
    const int*   __restrict__ de,
    const float* __restrict__ nodew,
    const float* __restrict__ wc,
    const float* __restrict__ ws,
    const float* __restrict__ w0)
{
    __shared__ __align__(16) __half pqin[4][32][40];  // [edge][P 0..15 | Q 16..31]
    __shared__ __align__(16) int2   nsb[4][32];       // {tn, sn}
    __shared__ float sgb[4][32];

    const int lane = threadIdx.x & 31;
    const int wid  = threadIdx.x >> 5;
    __half (*pin)[40] = pqin[wid];

    const int gw = blockIdx.x * 4 + wid;
    const int m  = (gw >= 5000) ? 1 : 0;

    const int gid = lane >> 2;
    const int tq  = lane & 3;

    // A fragments (half): [mt][chunk c][4]
    unsigned afr[2][2][4];
#pragma unroll
    for (int mt = 0; mt < 2; mt++)
#pragma unroll
        for (int c = 0; c < 2; c++) {
            const int r0 = mt * 16 + gid, r1 = r0 + 8;
            const int k0 = c * 16 + 2 * tq;
            const int k1 = k0 + 8;
            afr[mt][c][0] = packh2(loadW(wc, ws, r0, k0, m), loadW(wc, ws, r0, k0 + 1, m));
            afr[mt][c][1] = packh2(loadW(wc, ws, r1, k0, m), loadW(wc, ws, r1, k0 + 1, m));
            afr[mt][c][2] = packh2(loadW(wc, ws, r0, k1, m), loadW(wc, ws, r0, k1 + 1, m));
            afr[mt][c][3] = packh2(loadW(wc, ws, r1, k1, m), loadW(wc, ws, r1, k1 + 1, m));
        }

    const float w00 = __ldg(&w0[(gid +  0) * 2 + m]) + 1.0f;
    const float w01 = __ldg(&w0[(gid +  8) * 2 + m]) + 1.0f;
    const float w02 = __ldg(&w0[(gid + 16) * 2 + m]) + 1.0f;
    const float w03 = __ldg(&w0[(gid + 24) * 2 + m]) + 1.0f;

    const __half2* comb = g_combh + (long)m * BN * Kk;
    const int4*    de4  = reinterpret_cast<const int4*>(de);

    const int eo = lane >> 2;     // PQ: edge-of-8
    const int pj = lane & 3;      // PQ: 16B quad

    // ---- prologue: claim first tile + preload its edge record ----
    unsigned t = 0;
    if (lane == 0) t = atomicAdd(&g_ctr[m], 1u);
    t = __shfl_sync(0xffffffffu, t, 0);
    int4 dv = make_int4(0, 0, 0, 0);
    float nwv = 0.0f;
    if (t < NTm) {
        dv  = __ldg(&de4[(long)t * 32 + lane]);
        nwv = __ldg(&nodew[((long)t * 32 + lane) * 2 + m]);
    }

    while (t < NTm) {
        // claim next tile + prefetch its record (hidden behind PQ + MMA)
        unsigned t1 = 0;
        if (lane == 0) t1 = atomicAdd(&g_ctr[m], 1u);
        t1 = __shfl_sync(0xffffffffu, t1, 0);

        const int b  = (int)(t / 10000u);
        const int tn = b * Nn + (m ? dv.y : dv.x);
        const int sn = b * Nn + (m ? dv.w : dv.z);
        nsb[wid][lane] = make_int2(tn, sn);

        // geo gathers: issued now, consumed after PQ
        const float4 gt = g_geo[tn];
        const float4 gs = g_geo[sn];

        int4 dvn = dv; float nwn = nwv;
        if (t1 < NTm) {
            dvn = __ldg(&de4[(long)t1 * 32 + lane]);
            nwn = __ldg(&nodew[((long)t1 * 32 + lane) * 2 + m]);
        }
        __syncwarp();   // nsb visible

        // ---- PQ phase: 4 iterations x 8 edges; lane = (eo, pj) ----
#pragma unroll
        for (int pr = 0; pr < 4; pr++) {
            const int e   = pr * 8 + eo;
            const int2 ns = nsb[wid][e];
            const uint2 Tu0 = *reinterpret_cast<const uint2*>(&comb[(long)ns.x * Kk + 4 * pj]);
            const uint2 Tu1 = *reinterpret_cast<const uint2*>(&comb[(long)ns.x * Kk + 4 * pj + 2]);
            const uint2 Su0 = *reinterpret_cast<const uint2*>(&comb[(long)ns.y * Kk + 4 * pj]);
            const uint2 Su1 = *reinterpret_cast<const uint2*>(&comb[(long)ns.y * Kk + 4 * pj + 2]);
            const __half2 T[4] = {*(__half2*)&Tu0.x, *(__half2*)&Tu0.y,
                                  *(__half2*)&Tu1.x, *(__half2*)&Tu1.y};
            const __half2 S[4] = {*(__half2*)&Su0.x, *(__half2*)&Su0.y,
                                  *(__half2*)&Su1.x, *(__half2*)&Su1.y};
            __half P[4], Q[4];
#pragma unroll
            for (int k = 0; k < 4; k++) {
                const __half2 pp = __hmul2(T[k], S[k]);                    // (bct*bcs, bst*bss)
                const __half2 qq = __hmul2(T[k], __lowhigh2highlow(S[k])); // (bct*bss, bst*bcs)
                P[k] = __hadd(__low2half(pp), __high2half(pp));
                Q[k] = __hsub(__low2half(qq), __high2half(qq));
            }
            *reinterpret_cast<uint2*>(&pin[e][4 * pj]) =
                make_uint2(h2u(__halves2half2(P[0], P[1])), h2u(__halves2half2(P[2], P[3])));
            *reinterpret_cast<uint2*>(&pin[e][16 + 4 * pj]) =
                make_uint2(h2u(__halves2half2(Q[0], Q[1])), h2u(__halves2half2(Q[2], Q[3])));
        }

        // ---- geometry math (geo arrived during PQ) ----
        {
            const float dx = gt.x - gs.x, dy = gt.y - gs.y;
            const float r2 = fmaf(dx, dx, fmaf(dy, dy, 1e-6f));
            const float gr = fmaf(dx, gs.z, dy * gs.w) / r2;
            sgb[wid][lane] = gr * nwv;
        }
        __syncwarp();   // pin + sgb visible

        // ---- MMA (m16n8k16) + fused epilogue per nt ----
#pragma unroll
        for (int nt = 0; nt < 4; nt++) {
            const __half* prow = pin[nt * 8 + gid];
            float acc0[4] = {0.f, 0.f, 0.f, 0.f};   // rows gid, gid+8
            float acc1[4] = {0.f, 0.f, 0.f, 0.f};   // rows gid+16, gid+24
#pragma unroll
            for (int c = 0; c < 2; c++) {
                const unsigned b0 = *reinterpret_cast<const unsigned*>(&prow[16 * c + 2 * tq]);
                const unsigned b1 = *reinterpret_cast<const unsigned*>(&prow[16 * c + 2 * tq + 8]);
                mma_f16(acc0, afr[0][c], b0, b1);
                mma_f16(acc1, afr[1][c], b0, b1);
            }
            const int ed = nt * 8 + 2 * tq;
#pragma unroll
            for (int h = 0; h < 2; h++) {
                const int2 ns  = nsb[wid][ed + h];
                const float sg = sgb[wid][ed + h];
                const uint2 fu = *reinterpret_cast<const uint2*>(&g_fTh[(long)ns.y * 32 + 4 * gid]);
                const float2 f01 = __half22float2(*(const __half2*)&fu.x);
                const float2 f23 = __half22float2(*(const __half2*)&fu.y);
                const float v0 = (w00 + acc0[h])     * f01.x * sg;
                const float v1 = (w01 + acc0[2 + h]) * f01.y * sg;
                const float v2 = (w02 + acc1[h])     * f23.x * sg;
                const float v3 = (w03 + acc1[2 + h]) * f23.y * sg;
                float* dst = &g_fout[(long)ns.x * 32 + 4 * gid];
                asm volatile(
                    "red.global.add.v4.f32 [%0], {%1, %2, %3, %4};"
                    :: "l"(dst), "f"(v0), "f"(v1), "f"(v2), "f"(v3)
                    : "memory");
            }
        }
        __syncwarp();   // WAR: nsb/sgb/pin reused next iteration

        t = t1; dv = dvn; nwv = nwn;
    }
}

// ---------------------------------------------------------------------------
// Kernel 3: out[b,o,n] = sum_i w[o,i] * f_out_permuted[b,n,pi(i)] + bias[o]
// 64-node tiles, float4 fill.
// ---------------------------------------------------------------------------
__global__ void __launch_bounds__(256) out_kernel(
    const float* __restrict__ wk,
    const float* __restrict__ bias,
    float* __restrict__ out)
{
    __shared__ float fsm[64][33];
    __shared__ float wsm[COUTc][CINc];

    const int b   = blockIdx.y;
    const int n0  = blockIdx.x * 64;
    const int tid = threadIdx.x;
    const int nn  = min(64, Nn - n0);   // tail tile: Nn % 64 = 32

    for (int j = tid; j < COUTc * CINc; j += 256) {
        const int o = j / CINc, i = j % CINc;
        wsm[o][4 * (i & 7) + (i >> 3)] = wk[j];
    }

    // fill: 64 nodes x 8 float4 = 512 float4 loads, 2 per thread
#pragma unroll
    for (int j = 0; j < 2; j++) {
        const int idx = j * 256 + tid;       // 0..511
        const int nl = idx >> 3, q = idx & 7;
        if (nl < nn) {
            const float4 v = *reinterpret_cast<const float4*>(
                &g_fout[((long)b * Nn + n0 + nl) * CINc + q * 4]);
            fsm[nl][q * 4 + 0] = v.x;
            fsm[nl][q * 4 + 1] = v.y;
            fsm[nl][q * 4 + 2] = v.z;
            fsm[nl][q * 4 + 3] = v.w;
        }
    }
    __syncthreads();

    // compute: 64 nodes x 32 outputs = 2048 elems, 8 per thread
#pragma unroll
    for (int j = 0; j < 8; j++) {
        const int idx = j * 256 + tid;           // 0..2047
        const int o = idx >> 6, nl = idx & 63;   // o uniform within half-warp pair
        if (nl < nn) {
            float acc = bias[o];
#pragma unroll
            for (int i = 0; i < CINc; i++)
                acc = fmaf(wsm[o][i], fsm[nl][i], acc);
            out[((long)b * COUTc + o) * Nn + n0 + nl] = acc;
        }
    }
}

// ---------------------------------------------------------------------------
extern "C" void kernel_launch(void* const* d_in, const int* in_sizes, int n_in,
                              void* d_out, int out_size)
{
    const float* f    = (const float*)d_in[0];
    const float* bc   = (const float*)d_in[1];
    const float* bs   = (const float*)d_in[2];
    const float* nodes= (const float*)d_in[4];
    const float* nvec = (const float*)d_in[5];
    const int*   de   = (const int*)  d_in[6];
    const float* nw   = (const float*)d_in[7];
    const float* wc   = (const float*)d_in[8];
    const float* ws   = (const float*)d_in[9];
    const float* w0   = (const float*)d_in[10];
    const float* wk   = (const float*)d_in[11];
    const float* wb   = (const float*)d_in[12];
    float* out = (float*)d_out;

    prep_kernel<<<dim3(Nn / 32, Bsz), dim3(32, 8)>>>(f, bc, bs, nodes, nvec);
    edge_kernel<<<2500, 128>>>(de, nw, wc, ws, w0);
    out_kernel<<<dim3((Nn + 63) / 64, Bsz), 256>>>(wk, wb, out);
}

// round 16
// speedup vs baseline: 1.0361x; 1.0230x over previous
#include <cuda_runtime.h>
#include <cuda_fp16.h>

#define Bsz   4
#define Nn    20000
#define Ee    320000
#define CINc  32
#define COUTc 32
#define Kk    16
#define Mm    2
#define BN    (Bsz * Nn)
#define NTm   40000      // tiles per measure = Bsz * Ee / 32
#define NBLK  888        // persistent blocks (148 SMs x ~6)
#define WPMh  ((NBLK * 4) / 2)   // warps per measure = 1776

// Scratch. Channel-permuted layout: slot pi(r) = 4*(r&7) + (r>>3)
__device__ float   g_fout[BN * CINc];         // fp32 accumulator, permuted channels
__device__ __half  g_fTh[BN * CINc];          // fp16 fT, permuted channels, 64B/row
__device__ __half2 g_combh[Mm * BN * Kk];     // (bc,bs) per k: 64B per (m,node)
__device__ float4  g_geo[BN];                 // {x, y, nvx, nvy}
__device__ unsigned g_ctr[2];                 // dynamic tile queues (per measure)

__device__ __forceinline__ unsigned packh2(float lo, float hi) {
    __half2 h = __floats2half2_rn(lo, hi);
    return *reinterpret_cast<unsigned*>(&h);
}

__device__ __forceinline__ unsigned h2u(__half2 h) {
    return *reinterpret_cast<unsigned*>(&h);
}

__device__ __forceinline__ void mma_f16(float c[4], const unsigned a[4],
                                        unsigned b0, unsigned b1) {
    asm volatile(
        "mma.sync.aligned.m16n8k16.row.col.f32.f16.f16.f32 "
        "{%0,%1,%2,%3}, {%4,%5,%6,%7}, {%8,%9}, {%0,%1,%2,%3};"
        : "+f"(c[0]), "+f"(c[1]), "+f"(c[2]), "+f"(c[3])
        : "r"(a[0]), "r"(a[1]), "r"(a[2]), "r"(a[3]), "r"(b0), "r"(b1));
}

// ---------------------------------------------------------------------------
// Kernel 1: fT (fp16, permuted) + zero fout + pack comb (half2) + geo + ctr
// ---------------------------------------------------------------------------
__global__ void prep_kernel(const float* __restrict__ f,
                            const float* __restrict__ bc,
                            const float* __restrict__ bs,
                            const float* __restrict__ nodes,
                            const float* __restrict__ nvec)
{
    __shared__ float tile[32][33];
    const int b   = blockIdx.y;
    const int n0  = blockIdx.x * 32;
    const int tx  = threadIdx.x;
    const int ty  = threadIdx.y;
    const int tid = ty * 32 + tx;

    if (blockIdx.x == 0 && blockIdx.y == 0 && tid < 2) g_ctr[tid] = 0u;

#pragma unroll
    for (int r = 0; r < 4; r++) {
        int ci = ty + 8 * r;
        tile[ci][tx] = f[((long)b * CINc + ci) * Nn + n0 + tx];
    }

    if (tid < 32) {
        const long node = (long)b * Nn + n0 + tid;
        const float2 p  = reinterpret_cast<const float2*>(nodes)[node];
        const float2 nv = reinterpret_cast<const float2*>(nvec)[node];
        g_geo[node] = make_float4(p.x, p.y, nv.x, nv.y);
    }

    {
        const int nl = tid >> 3;
        const int pj = tid & 7;
        const long node = (long)b * Nn + n0 + nl;
        const float4 A = *reinterpret_cast<const float4*>(&bc[node * 32 + pj * 4]);
        const float4 B = *reinterpret_cast<const float4*>(&bs[node * 32 + pj * 4]);
        __half2* c0 = &g_combh[(0L * BN + node) * Kk + 2 * pj];
        __half2* c1 = &g_combh[(1L * BN + node) * Kk + 2 * pj];
        c0[0] = __floats2half2_rn(A.x, B.x);
        c0[1] = __floats2half2_rn(A.z, B.z);
        c1[0] = __floats2half2_rn(A.y, B.y);
        c1[1] = __floats2half2_rn(A.w, B.w);
    }

    __syncthreads();
    const int pix = 4 * (tx & 7) + (tx >> 3);
#pragma unroll
    for (int r = 0; r < 4; r++) {
        int nl = ty + 8 * r;
        long base = ((long)b * Nn + n0 + nl) * CINc;
        g_fTh[base + pix] = __float2half(tile[tx][nl]);
        g_fout[base + tx] = 0.0f;
    }
}

// ---------------------------------------------------------------------------
__device__ __forceinline__ float loadW(const float* __restrict__ wc,
                                       const float* __restrict__ ws,
                                       int r, int c, int m)
{
    return (c < 16) ? 2.0f * __ldg(&wc[r * 32 + c * 2 + m])
                    : 2.0f * __ldg(&ws[r * 32 + (c - 16) * 2 + m]);
}

// ---------------------------------------------------------------------------
// Kernel 2: edge scatter, fp16 mma, pipelined, dynamic queue, persistent grid.
// ---------------------------------------------------------------------------
__global__ void __launch_bounds__(128) edge_kernel(
    const int*   __restrict__ de,
    const float* __restrict__ nodew,
    const float* __restrict__ wc,
    const float* __restrict__ ws,
    const float* __restrict__ w0)
{
    __shared__ __align__(16) __half pqin[4][32][40];  // [edge][P 0..15 | Q 16..31]
    __shared__ __align__(16) int2   nsb[4][32];       // {tn, sn}
    __shared__ float sgb[4][32];

    const int lane = threadIdx.x & 31;
    const int wid  = threadIdx.x >> 5;
    __half (*pin)[40] = pqin[wid];

    const int gw = blockIdx.x * 4 + wid;
    const int m  = (gw >= WPMh) ? 1 : 0;

    const int gid = lane >> 2;
    const int tq  = lane & 3;

    // A fragments (half): [mt][chunk c][4]
    unsigned afr[2][2][4];
#pragma unroll
    for (int mt = 0; mt < 2; mt++)
#pragma unroll
        for (int c = 0; c < 2; c++) {
            const int r0 = mt * 16 + gid, r1 = r0 + 8;
            const int k0 = c * 16 + 2 * tq;
            const int k1 = k0 + 8;
            afr[mt][c][0] = packh2(loadW(wc, ws, r0, k0, m), loadW(wc, ws, r0, k0 + 1, m));
            afr[mt][c][1] = packh2(loadW(wc, ws, r1, k0, m), loadW(wc, ws, r1, k0 + 1, m));
            afr[mt][c][2] = packh2(loadW(wc, ws, r0, k1, m), loadW(wc, ws, r0, k1 + 1, m));
            afr[mt][c][3] = packh2(loadW(wc, ws, r1, k1, m), loadW(wc, ws, r1, k1 + 1, m));
        }

    const float w00 = __ldg(&w0[(gid +  0) * 2 + m]) + 1.0f;
    const float w01 = __ldg(&w0[(gid +  8) * 2 + m]) + 1.0f;
    const float w02 = __ldg(&w0[(gid + 16) * 2 + m]) + 1.0f;
    const float w03 = __ldg(&w0[(gid + 24) * 2 + m]) + 1.0f;

    const __half2* comb = g_combh + (long)m * BN * Kk;
    const int4*    de4  = reinterpret_cast<const int4*>(de);

    const int eo = lane >> 2;     // PQ: edge-of-8
    const int pj = lane & 3;      // PQ: 16B quad

    // ---- prologue: claim first tile + preload its edge record ----
    unsigned t = 0;
    if (lane == 0) t = atomicAdd(&g_ctr[m], 1u);
    t = __shfl_sync(0xffffffffu, t, 0);
    int4 dv = make_int4(0, 0, 0, 0);
    float nwv = 0.0f;
    if (t < NTm) {
        dv  = __ldg(&de4[(long)t * 32 + lane]);
        nwv = __ldg(&nodew[((long)t * 32 + lane) * 2 + m]);
    }

    while (t < NTm) {
        // claim next tile + prefetch its record (hidden behind PQ + MMA)
        unsigned t1 = 0;
        if (lane == 0) t1 = atomicAdd(&g_ctr[m], 1u);
        t1 = __shfl_sync(0xffffffffu, t1, 0);

        const int b  = (int)(t / 10000u);
        const int tn = b * Nn + (m ? dv.y : dv.x);
        const int sn = b * Nn + (m ? dv.w : dv.z);
        nsb[wid][lane] = make_int2(tn, sn);

        // geo gathers: issued now, consumed after PQ
        const float4 gt = g_geo[tn];
        const float4 gs = g_geo[sn];

        int4 dvn = dv; float nwn = nwv;
        if (t1 < NTm) {
            dvn = __ldg(&de4[(long)t1 * 32 + lane]);
            nwn = __ldg(&nodew[((long)t1 * 32 + lane) * 2 + m]);
        }
        __syncwarp();   // nsb visible

        // ---- PQ phase: 4 iterations x 8 edges; lane = (eo, pj) ----
#pragma unroll
        for (int pr = 0; pr < 4; pr++) {
            const int e   = pr * 8 + eo;
            const int2 ns = nsb[wid][e];
            const uint2 Tu0 = *reinterpret_cast<const uint2*>(&comb[(long)ns.x * Kk + 4 * pj]);
            const uint2 Tu1 = *reinterpret_cast<const uint2*>(&comb[(long)ns.x * Kk + 4 * pj + 2]);
            const uint2 Su0 = *reinterpret_cast<const uint2*>(&comb[(long)ns.y * Kk + 4 * pj]);
            const uint2 Su1 = *reinterpret_cast<const uint2*>(&comb[(long)ns.y * Kk + 4 * pj + 2]);
            const __half2 T[4] = {*(__half2*)&Tu0.x, *(__half2*)&Tu0.y,
                                  *(__half2*)&Tu1.x, *(__half2*)&Tu1.y};
            const __half2 S[4] = {*(__half2*)&Su0.x, *(__half2*)&Su0.y,
                                  *(__half2*)&Su1.x, *(__half2*)&Su1.y};
            __half P[4], Q[4];
#pragma unroll
            for (int k = 0; k < 4; k++) {
                const __half2 pp = __hmul2(T[k], S[k]);                    // (bct*bcs, bst*bss)
                const __half2 qq = __hmul2(T[k], __lowhigh2highlow(S[k])); // (bct*bss, bst*bcs)
                P[k] = __hadd(__low2half(pp), __high2half(pp));
                Q[k] = __hsub(__low2half(qq), __high2half(qq));
            }
            *reinterpret_cast<uint2*>(&pin[e][4 * pj]) =
                make_uint2(h2u(__halves2half2(P[0], P[1])), h2u(__halves2half2(P[2], P[3])));
            *reinterpret_cast<uint2*>(&pin[e][16 + 4 * pj]) =
                make_uint2(h2u(__halves2half2(Q[0], Q[1])), h2u(__halves2half2(Q[2], Q[3])));
        }

        // ---- geometry math (geo arrived during PQ) ----
        {
            const float dx = gt.x - gs.x, dy = gt.y - gs.y;
            const float r2 = fmaf(dx, dx, fmaf(dy, dy, 1e-6f));
            const float gr = fmaf(dx, gs.z, dy * gs.w) / r2;
            sgb[wid][lane] = gr * nwv;
        }
        __syncwarp();   // pin + sgb visible

        // ---- MMA (m16n8k16) + fused epilogue per nt ----
#pragma unroll
        for (int nt = 0; nt < 4; nt++) {
            const __half* prow = pin[nt * 8 + gid];
            float acc0[4] = {0.f, 0.f, 0.f, 0.f};   // rows gid, gid+8
            float acc1[4] = {0.f, 0.f, 0.f, 0.f};   // rows gid+16, gid+24
#pragma unroll
            for (int c = 0; c < 2; c++) {
                const unsigned b0 = *reinterpret_cast<const unsigned*>(&prow[16 * c + 2 * tq]);
                const unsigned b1 = *reinterpret_cast<const unsigned*>(&prow[16 * c + 2 * tq + 8]);
                mma_f16(acc0, afr[0][c], b0, b1);
                mma_f16(acc1, afr[1][c], b0, b1);
            }
            const int ed = nt * 8 + 2 * tq;
#pragma unroll
            for (int h = 0; h < 2; h++) {
                const int2 ns  = nsb[wid][ed + h];
                const float sg = sgb[wid][ed + h];
                const uint2 fu = *reinterpret_cast<const uint2*>(&g_fTh[(long)ns.y * 32 + 4 * gid]);
                const float2 f01 = __half22float2(*(const __half2*)&fu.x);
                const float2 f23 = __half22float2(*(const __half2*)&fu.y);
                const float v0 = (w00 + acc0[h])     * f01.x * sg;
                const float v1 = (w01 + acc0[2 + h]) * f01.y * sg;
                const float v2 = (w02 + acc1[h])     * f23.x * sg;
                const float v3 = (w03 + acc1[2 + h]) * f23.y * sg;
                float* dst = &g_fout[(long)ns.x * 32 + 4 * gid];
                asm volatile(
                    "red.global.add.v4.f32 [%0], {%1, %2, %3, %4};"
                    :: "l"(dst), "f"(v0), "f"(v1), "f"(v2), "f"(v3)
                    : "memory");
            }
        }
        __syncwarp();   // WAR: nsb/sgb/pin reused next iteration

        t = t1; dv = dvn; nwv = nwn;
    }
}

// ---------------------------------------------------------------------------
// Kernel 3: out[b,o,n] = sum_i w[o,i] * f_out_permuted[b,n,pi(i)] + bias[o]
// 64-node tiles, float4 fill.
// ---------------------------------------------------------------------------
__global__ void __launch_bounds__(256) out_kernel(
    const float* __restrict__ wk,
    const float* __restrict__ bias,
    float* __restrict__ out)
{
    __shared__ float fsm[64][33];
    __shared__ float wsm[COUTc][CINc];

    const int b   = blockIdx.y;
    const int n0  = blockIdx.x * 64;
    const int tid = threadIdx.x;
    const int nn  = min(64, Nn - n0);   // tail tile: Nn % 64 = 32

    for (int j = tid; j < COUTc * CINc; j += 256) {
        const int o = j / CINc, i = j % CINc;
        wsm[o][4 * (i & 7) + (i >> 3)] = wk[j];
    }

    // fill: 64 nodes x 8 float4 = 512 float4 loads, 2 per thread
#pragma unroll
    for (int j = 0; j < 2; j++) {
        const int idx = j * 256 + tid;       // 0..511
        const int nl = idx >> 3, q = idx & 7;
        if (nl < nn) {
            const float4 v = *reinterpret_cast<const float4*>(
                &g_fout[((long)b * Nn + n0 + nl) * CINc + q * 4]);
            fsm[nl][q * 4 + 0] = v.x;
            fsm[nl][q * 4 + 1] = v.y;
            fsm[nl][q * 4 + 2] = v.z;
            fsm[nl][q * 4 + 3] = v.w;
        }
    }
    __syncthreads();

    // compute: 64 nodes x 32 outputs = 2048 elems, 8 per thread
#pragma unroll
    for (int j = 0; j < 8; j++) {
        const int idx = j * 256 + tid;           // 0..2047
        const int o = idx >> 6, nl = idx & 63;
        if (nl < nn) {
            float acc = bias[o];
#pragma unroll
            for (int i = 0; i < CINc; i++)
                acc = fmaf(wsm[o][i], fsm[nl][i], acc);
            out[((long)b * COUTc + o) * Nn + n0 + nl] = acc;
        }
    }
}

// ---------------------------------------------------------------------------
extern "C" void kernel_launch(void* const* d_in, const int* in_sizes, int n_in,
                              void* d_out, int out_size)
{
    const float* f    = (const float*)d_in[0];
    const float* bc   = (const float*)d_in[1];
    const float* bs   = (const float*)d_in[2];
    const float* nodes= (const float*)d_in[4];
    const float* nvec = (const float*)d_in[5];
    const int*   de   = (const int*)  d_in[6];
    const float* nw   = (const float*)d_in[7];
    const float* wc   = (const float*)d_in[8];
    const float* ws   = (const float*)d_in[9];
    const float* w0   = (const float*)d_in[10];
    const float* wk   = (const float*)d_in[11];
    const float* wb   = (const float*)d_in[12];
    float* out = (float*)d_out;

    prep_kernel<<<dim3(Nn / 32, Bsz), dim3(32, 8)>>>(f, bc, bs, nodes, nvec);
    edge_kernel<<<NBLK, 128>>>(de, nw, wc, ws, w0);
    out_kernel<<<dim3((Nn + 63) / 64, Bsz), 256>>>(wk, wb, out);
}